// round 13
// baseline (speedup 1.0000x reference)
#include <cuda_runtime.h>
#include <cuda_bf16.h>
#include <cstdint>

#define BATCH 8
#define SEQ   2048
#define DIM   256
#define HEADS 8
#define BQ 64
#define BK 64
#define NTHR 512
#define NP (BATCH * (SEQ + 1) * DIM)
#define NE (BATCH * SEQ * DIM)

// ---- attn smem byte offsets ----
#define OFF_QH 0
#define OFF_QL 32768
#define OFF_KH 65536
#define OFF_KL 98304
#define OFF_EH 131072          // EW hi tile
#define OFF_EL 163840          // EW lo tile
#define OFF_PH 196608
#define OFF_PL 204800
#define OFF_RS 212992
#define SMEM_TOTAL (OFF_RS + 256)

// ---- ew kernel smem: E tiles + double-buffered W chunks (80B row stride) ----
#define EW_EH 0
#define EW_EL 32768
#define EW_W0 65536
#define EW_WSTRIDE 20480       // 256 rows x 80B
#define EW_W1 (EW_W0 + EW_WSTRIDE)
#define EW_SMEM (EW_W1 + EW_WSTRIDE)   // 106496 <= 113KB -> 2 CTAs/SM

// pre-split operands (bf16 bits as ushort)
__device__ __align__(16) unsigned short g_ph[NP];
__device__ __align__(16) unsigned short g_pl[NP];
__device__ __align__(16) unsigned short g_Wh[DIM * DIM];
__device__ __align__(16) unsigned short g_Wl[DIM * DIM];
__device__ __align__(16) unsigned short g_ewh[NE];
__device__ __align__(16) unsigned short g_ewl[NE];

// ---- helpers ----
__device__ __forceinline__ uint32_t smem_u32(const void* p) {
    uint32_t a;
    asm("{ .reg .u64 t; cvta.to.shared.u64 t, %1; cvt.u32.u64 %0, t; }" : "=r"(a) : "l"(p));
    return a;
}
__device__ __forceinline__ void cp16(uint32_t dst, const void* src) {
    asm volatile("cp.async.cg.shared.global [%0], [%1], 16;" :: "r"(dst), "l"(src));
}
#define CP_COMMIT() asm volatile("cp.async.commit_group;" ::: "memory")
#define CP_WAIT0()  asm volatile("cp.async.wait_group 0;" ::: "memory")
#define CP_WAIT1()  asm volatile("cp.async.wait_group 1;" ::: "memory")

__device__ __forceinline__ void ldsm4(uint32_t addr, uint32_t& r0, uint32_t& r1, uint32_t& r2, uint32_t& r3) {
    asm volatile("ldmatrix.sync.aligned.m8n8.x4.shared.b16 {%0,%1,%2,%3}, [%4];"
                 : "=r"(r0), "=r"(r1), "=r"(r2), "=r"(r3) : "r"(addr));
}
__device__ __forceinline__ void ldsm4t(uint32_t addr, uint32_t& r0, uint32_t& r1, uint32_t& r2, uint32_t& r3) {
    asm volatile("ldmatrix.sync.aligned.m8n8.x4.trans.shared.b16 {%0,%1,%2,%3}, [%4];"
                 : "=r"(r0), "=r"(r1), "=r"(r2), "=r"(r3) : "r"(addr));
}
__device__ __forceinline__ void mma16816(float* c, uint32_t a0, uint32_t a1, uint32_t a2, uint32_t a3,
                                         uint32_t b0, uint32_t b1) {
    asm volatile("mma.sync.aligned.m16n8k16.row.col.f32.bf16.bf16.f32 "
                 "{%0,%1,%2,%3}, {%4,%5,%6,%7}, {%8,%9}, {%0,%1,%2,%3};"
                 : "+f"(c[0]), "+f"(c[1]), "+f"(c[2]), "+f"(c[3])
                 : "r"(a0), "r"(a1), "r"(a2), "r"(a3), "r"(b0), "r"(b1));
}
__device__ __forceinline__ void split2(float x0, float x1, unsigned& hp, unsigned& lp) {
    __nv_bfloat16 h0 = __float2bfloat16_rn(x0);
    __nv_bfloat16 h1 = __float2bfloat16_rn(x1);
    __nv_bfloat16 l0 = __float2bfloat16_rn(x0 - __bfloat162float(h0));
    __nv_bfloat16 l1 = __float2bfloat16_rn(x1 - __bfloat162float(h1));
    hp = (unsigned)__bfloat16_as_ushort(h0) | ((unsigned)__bfloat16_as_ushort(h1) << 16);
    lp = (unsigned)__bfloat16_as_ushort(l0) | ((unsigned)__bfloat16_as_ushort(l1) << 16);
}
#define SWZ(row, colb) ((uint32_t)(colb) ^ (((uint32_t)(row) & 7u) << 4))

// 512B-row tile: split + store 4 consecutive cols (hi/lo)
__device__ __forceinline__ void store_split4_512(char* bh, char* bl, int row, int col, float4 v) {
    unsigned h0, l0, h1, l1;
    split2(v.x, v.y, h0, l0);
    split2(v.z, v.w, h1, l1);
    uint32_t off = (uint32_t)row * 512u + SWZ(row, col * 2);
    *(uint32_t*)(bh + off) = h0; *(uint32_t*)(bh + off + 4) = h1;
    *(uint32_t*)(bl + off) = l0; *(uint32_t*)(bl + off + 4) = l1;
}

// ---------------------------------------------------------------------------
// split p into hi/lo bf16 (vectorized x4)
// ---------------------------------------------------------------------------
__global__ void split_p_kernel(const float4* __restrict__ p4) {
    int i = blockIdx.x * blockDim.x + threadIdx.x;
    if (i < NP / 4) {
        float4 v = p4[i];
        unsigned h01, l01, h23, l23;
        split2(v.x, v.y, h01, l01);
        split2(v.z, v.w, h23, l23);
        *(uint2*)(g_ph + 4 * (size_t)i) = make_uint2(h01, h23);
        *(uint2*)(g_pl + 4 * (size_t)i) = make_uint2(l01, l23);
    }
}

// W_eff[n][k] = sum_h W_o[n, h*DIM + k], split
__global__ void weff_kernel(const float* __restrict__ Wo) {
    int t = blockIdx.x * blockDim.x + threadIdx.x;
    int dout = t >> 8, din = t & 255;
    float s = 0.f;
#pragma unroll
    for (int h = 0; h < HEADS; h++)
        s += Wo[(size_t)dout * (DIM * HEADS) + h * DIM + din];
    __nv_bfloat16 hh = __float2bfloat16_rn(s);
    g_Wh[t] = __bfloat16_as_ushort(hh);
    g_Wl[t] = __bfloat16_as_ushort(__float2bfloat16_rn(s - __bfloat162float(hh)));
}

// ---------------------------------------------------------------------------
// EW = E @ Weff^T  (16384 x 256), bf16x3, double-buffered W-chunk pipeline.
// 256 CTAs x 64 rows, 256 threads (4 m-warps x 2 n-warps), 2 CTAs/SM.
// W chunk c = k-cols [c*16, c*16+16), stored 80B/row: [0:32) hi, [32:64) lo.
// ---------------------------------------------------------------------------
__global__ __launch_bounds__(256, 2)
void ew_kernel(const float* __restrict__ e) {
    extern __shared__ char smem[];
    const uint32_t sb = smem_u32(smem);
    const int tid  = threadIdx.x;
    const int lane = tid & 31;
    const int wid  = tid >> 5;
    const int mw   = wid & 3;
    const int nw   = wid >> 2;   // 0..1, 128 dims each
    const int rbase = (int)blockIdx.x * 64;

    // load + split E rows (64 x 256 fp32)
    {
        const int r  = tid >> 2;
        const int cb = (tid & 3) * 64;
        const float* er = e + (size_t)(rbase + r) * DIM + cb;
#pragma unroll
        for (int i = 0; i < 16; i++) {
            float4 v = *(const float4*)(er + i * 4);
            store_split4_512(smem + EW_EH, smem + EW_EL, r, cb + i * 4, v);
        }
    }

    // prefetch W chunk 0 into buffer 0
    {
        const unsigned short* wh = g_Wh + (size_t)tid * 256;
        const unsigned short* wl = g_Wl + (size_t)tid * 256;
        const uint32_t ro = sb + EW_W0 + (uint32_t)tid * 80u;
        cp16(ro, wh); cp16(ro + 16, wh + 8);
        cp16(ro + 32, wl); cp16(ro + 48, wl + 8);
        CP_COMMIT();
    }

    float pacc[16][4];
#pragma unroll
    for (int i = 0; i < 16; i++)
#pragma unroll
        for (int j = 0; j < 4; j++) pacc[i][j] = 0.f;

    const int ar = mw * 16 + (lane & 15);
    const uint32_t kb = (uint32_t)(((lane >> 3) & 1) << 4);

    for (int c = 0; c < 16; c++) {
        __syncthreads();    // readers of chunk c-1 done -> safe to overwrite its buffer
        if (c < 15) {       // prefetch chunk c+1
            const unsigned short* wh = g_Wh + (size_t)tid * 256 + (c + 1) * 16;
            const unsigned short* wl = g_Wl + (size_t)tid * 256 + (c + 1) * 16;
            const uint32_t ro = sb + (((c + 1) & 1) ? EW_W1 : EW_W0) + (uint32_t)tid * 80u;
            cp16(ro, wh); cp16(ro + 16, wh + 8);
            cp16(ro + 32, wl); cp16(ro + 48, wl + 8);
        }
        CP_COMMIT();
        CP_WAIT1();         // chunk c complete (chunk c+1 pending)
        __syncthreads();    // chunk c visible

        const uint32_t wbuf = sb + ((c & 1) ? EW_W1 : EW_W0);
        const uint32_t acb = (uint32_t)(c * 32 + ((lane >> 4) << 4));
        const uint32_t aoff = (uint32_t)ar * 512u + SWZ(ar, acb);
        uint32_t e0, e1, e2, e3, e4, e5, e6, e7;
        ldsm4(sb + EW_EH + aoff, e0, e1, e2, e3);
        ldsm4(sb + EW_EL + aoff, e4, e5, e6, e7);
#pragma unroll
        for (int pt = 0; pt < 8; pt++) {
            const int dout2 = nw * 128 + pt * 16 + (lane & 7) + ((lane >> 4) << 3);
            const uint32_t wrow = wbuf + (uint32_t)dout2 * 80u;
            uint32_t wh0, wh1, wh2, wh3, wl0, wl1, wl2, wl3;
            ldsm4(wrow + kb, wh0, wh1, wh2, wh3);
            ldsm4(wrow + 32 + kb, wl0, wl1, wl2, wl3);
            float* c0 = pacc[2 * pt];
            float* c1 = pacc[2 * pt + 1];
            mma16816(c0, e0, e1, e2, e3, wh0, wh1);
            mma16816(c1, e0, e1, e2, e3, wh2, wh3);
            mma16816(c0, e0, e1, e2, e3, wl0, wl1);
            mma16816(c1, e0, e1, e2, e3, wl2, wl3);
            mma16816(c0, e4, e5, e6, e7, wh0, wh1);
            mma16816(c1, e4, e5, e6, e7, wh2, wh3);
        }
    }

    // write EW split hi/lo
    const int r0 = rbase + mw * 16 + (lane >> 2);
    const int r1 = r0 + 8;
#pragma unroll
    for (int nt = 0; nt < 16; nt++) {
        const int col = nw * 128 + nt * 8 + (lane & 3) * 2;
        unsigned h, l;
        split2(pacc[nt][0], pacc[nt][1], h, l);
        *(uint32_t*)(g_ewh + (size_t)r0 * DIM + col) = h;
        *(uint32_t*)(g_ewl + (size_t)r0 * DIM + col) = l;
        split2(pacc[nt][2], pacc[nt][3], h, l);
        *(uint32_t*)(g_ewh + (size_t)r1 * DIM + col) = h;
        *(uint32_t*)(g_ewl + (size_t)r1 * DIM + col) = l;
    }
}

// ---------------------------------------------------------------------------
// Fused attention (projection pre-folded into EW), mma.sync bf16x3, paired
// q-tiles, 3 barriers per key tile. 512 threads = 16 warps: 4 mw x 4 nw.
// ---------------------------------------------------------------------------
__global__ __launch_bounds__(NTHR, 1)
void attn_kernel(float* __restrict__ out) {
    extern __shared__ char smem[];
    const uint32_t sb = smem_u32(smem);
    const int tid  = threadIdx.x;
    const int lane = tid & 31;
    const int wid  = tid >> 5;
    const int mw   = wid & 3;
    const int nw   = wid >> 2;
    const int b    = blockIdx.y;
    const unsigned short* ph  = g_ph  + (size_t)b * (SEQ + 1) * DIM;
    const unsigned short* pl  = g_pl  + (size_t)b * (SEQ + 1) * DIM;
    const unsigned short* ewh = g_ewh + (size_t)b * SEQ * DIM;
    const unsigned short* ewl = g_ewl + (size_t)b * SEQ * DIM;
    float* rowsum = (float*)(smem + OFF_RS);

    const int row0 = mw * 16 + (lane >> 2);
    const int ar   = mw * 16 + (lane & 15);
    const int key  = nw * 16 + (lane & 7) + ((lane >> 4) << 3);
    const int ldr  = tid >> 3;
    const int lds0 = tid & 7;

    for (int pass = 0; pass < 2; pass++) {
        const int qt = pass ? (int)blockIdx.x : 31 - (int)blockIdx.x;
        const int q0 = qt * BQ;
        const int qg0 = q0 + row0, qg1 = qg0 + 8;
        const int qgmax = q0 + mw * 16 + 15;   // max query row of this warp
        if (tid < BQ) rowsum[tid] = 0.f;

        // ---- prologue: Q + K(0) (group 1), EW(0) (group 2) ----
        {
            const unsigned short* qh = ph + (size_t)(q0 + ldr + 1) * DIM;
            const unsigned short* ql = pl + (size_t)(q0 + ldr + 1) * DIM;
            const unsigned short* kh = ph + (size_t)ldr * DIM;
            const unsigned short* kl = pl + (size_t)ldr * DIM;
#pragma unroll
            for (int j = 0; j < 4; j++) {
                const int seg = lds0 + j * 8;
                const uint32_t off = (uint32_t)ldr * 512u + SWZ(ldr, seg * 16);
                cp16(sb + OFF_QH + off, qh + seg * 8);
                cp16(sb + OFF_QL + off, ql + seg * 8);
                cp16(sb + OFF_KH + off, kh + seg * 8);
                cp16(sb + OFF_KL + off, kl + seg * 8);
            }
            CP_COMMIT();
            const unsigned short* vh = ewh + (size_t)ldr * DIM;
            const unsigned short* vl = ewl + (size_t)ldr * DIM;
#pragma unroll
            for (int j = 0; j < 4; j++) {
                const int seg = lds0 + j * 8;
                const uint32_t off = (uint32_t)ldr * 512u + SWZ(ldr, seg * 16);
                cp16(sb + OFF_EH + off, vh + seg * 8);
                cp16(sb + OFF_EL + off, vl + seg * 8);
            }
            CP_COMMIT();
        }
        CP_WAIT1();              // Q + K(0) done; EW(0) pending
        __syncthreads();

        float yacc[8][4];
#pragma unroll
        for (int i = 0; i < 8; i++)
#pragma unroll
            for (int j = 0; j < 4; j++) yacc[i][j] = 0.f;
        float rs0 = 0.f, rs1 = 0.f;

        // ---- key-tile loop: invariant at entry: K(kt) visible, EW(kt) pending ----
        for (int kt = 0; kt <= qt; kt++) {
            const int k0 = kt * BK;
            const bool sActive = (k0 + nw * 16) <= qgmax;

            // S GEMM: warp tile 16 rows x 16 keys
            float sacc[2][4];
#pragma unroll
            for (int i = 0; i < 2; i++)
#pragma unroll
                for (int j = 0; j < 4; j++) sacc[i][j] = 0.f;
            if (sActive) {
#pragma unroll
                for (int ks = 0; ks < 16; ks++) {
                    const uint32_t acb = (uint32_t)(ks * 32 + ((lane >> 4) << 4));
                    const uint32_t aoff = (uint32_t)ar * 512u + SWZ(ar, acb);
                    uint32_t qh0, qh1, qh2, qh3, ql0, ql1, ql2, ql3;
                    ldsm4(sb + OFF_QH + aoff, qh0, qh1, qh2, qh3);
                    ldsm4(sb + OFF_QL + aoff, ql0, ql1, ql2, ql3);
                    const uint32_t kb = (uint32_t)(ks * 32 + (((lane >> 3) & 1) << 4));
                    const uint32_t koff = (uint32_t)key * 512u + SWZ(key, kb);
                    uint32_t kh0, kh1, kh2, kh3, kl0, kl1, kl2, kl3;
                    ldsm4(sb + OFF_KH + koff, kh0, kh1, kh2, kh3);
                    ldsm4(sb + OFF_KL + koff, kl0, kl1, kl2, kl3);
                    mma16816(sacc[0], qh0, qh1, qh2, qh3, kh0, kh1);
                    mma16816(sacc[1], qh0, qh1, qh2, qh3, kh2, kh3);
                    mma16816(sacc[0], qh0, qh1, qh2, qh3, kl0, kl1);
                    mma16816(sacc[1], qh0, qh1, qh2, qh3, kl2, kl3);
                    mma16816(sacc[0], ql0, ql1, ql2, ql3, kh0, kh1);
                    mma16816(sacc[1], ql0, ql1, ql2, ql3, kh2, kh3);
                }
            }

            // epilogue (register-only inputs): scale/clip/mask/exp; P -> smem
            if (sActive) {
#pragma unroll
                for (int nt = 0; nt < 2; nt++) {
                    const int colL = nw * 16 + nt * 8 + (lane & 3) * 2;
                    const int kgl = k0 + colL;
                    float s00 = fminf(10.f, fmaxf(-10.f, sacc[nt][0] * 0.0625f));
                    float s01 = fminf(10.f, fmaxf(-10.f, sacc[nt][1] * 0.0625f));
                    float s10 = fminf(10.f, fmaxf(-10.f, sacc[nt][2] * 0.0625f));
                    float s11 = fminf(10.f, fmaxf(-10.f, sacc[nt][3] * 0.0625f));
                    float w00 = (kgl     <= qg0) ? __expf(s00) : 0.f;
                    float w01 = (kgl + 1 <= qg0) ? __expf(s01) : 0.f;
                    float w10 = (kgl     <= qg1) ? __expf(s10) : 0.f;
                    float w11 = (kgl + 1 <= qg1) ? __expf(s11) : 0.f;
                    rs0 += w00 + w01;
                    rs1 += w10 + w11;
                    unsigned h, l;
                    uint32_t o0 = (uint32_t)row0 * 128u + SWZ(row0, colL * 2);
                    split2(w00, w01, h, l);
                    *(uint32_t*)(smem + OFF_PH + o0) = h;
                    *(uint32_t*)(smem + OFF_PL + o0) = l;
                    uint32_t o1 = (uint32_t)(row0 + 8) * 128u + SWZ(row0 + 8, colL * 2);
                    split2(w10, w11, h, l);
                    *(uint32_t*)(smem + OFF_PH + o1) = h;
                    *(uint32_t*)(smem + OFF_PL + o1) = l;
                }
            } else {
#pragma unroll
                for (int nt = 0; nt < 2; nt++) {
                    const int colL = nw * 16 + nt * 8 + (lane & 3) * 2;
                    uint32_t o0 = (uint32_t)row0 * 128u + SWZ(row0, colL * 2);
                    *(uint32_t*)(smem + OFF_PH + o0) = 0u;
                    *(uint32_t*)(smem + OFF_PL + o0) = 0u;
                    uint32_t o1 = (uint32_t)(row0 + 8) * 128u + SWZ(row0 + 8, colL * 2);
                    *(uint32_t*)(smem + OFF_PH + o1) = 0u;
                    *(uint32_t*)(smem + OFF_PL + o1) = 0u;
                }
            }

            CP_WAIT0();          // EW(kt) complete (only pending group)
            __syncthreads();     // A: K(kt) readers done; P(kt) + EW(kt) visible

            // prefetch K(kt+1)
            if (kt < qt) {
                const unsigned short* kh = ph + (size_t)(k0 + BK + ldr) * DIM;
                const unsigned short* kl = pl + (size_t)(k0 + BK + ldr) * DIM;
#pragma unroll
                for (int j = 0; j < 4; j++) {
                    const int seg = lds0 + j * 8;
                    const uint32_t off = (uint32_t)ldr * 512u + SWZ(ldr, seg * 16);
                    cp16(sb + OFF_KH + off, kh + seg * 8);
                    cp16(sb + OFF_KL + off, kl + seg * 8);
                }
            }
            CP_COMMIT();

            // AV GEMM (vs EW): warp tile 16 rows x 64 out-dims
#pragma unroll
            for (int ks = 0; ks < 4; ks++) {
                if (k0 + ks * 16 > qgmax) continue;   // P block all zero
                const uint32_t acb = (uint32_t)(ks * 32 + ((lane >> 4) << 4));
                const uint32_t aoff = (uint32_t)ar * 128u + SWZ(ar, acb);
                uint32_t p0, p1, p2, p3, p4, p5, p6, p7;
                ldsm4(sb + OFF_PH + aoff, p0, p1, p2, p3);
                ldsm4(sb + OFF_PL + aoff, p4, p5, p6, p7);
                const int key2 = ks * 16 + (lane & 15);
#pragma unroll
                for (int grp = 0; grp < 4; grp++) {
                    const uint32_t dcb = (uint32_t)((nw * 64 + grp * 16 + ((lane >> 4) << 3)) * 2);
                    const uint32_t eoff = (uint32_t)key2 * 512u + SWZ(key2, dcb);
                    uint32_t eh0, eh1, eh2, eh3, el0, el1, el2, el3;
                    ldsm4t(sb + OFF_EH + eoff, eh0, eh1, eh2, eh3);
                    ldsm4t(sb + OFF_EL + eoff, el0, el1, el2, el3);
                    float* y0 = yacc[2 * grp];
                    float* y1 = yacc[2 * grp + 1];
                    mma16816(y0, p0, p1, p2, p3, eh0, eh1);
                    mma16816(y1, p0, p1, p2, p3, eh2, eh3);
                    mma16816(y0, p0, p1, p2, p3, el0, el1);
                    mma16816(y1, p0, p1, p2, p3, el2, el3);
                    mma16816(y0, p4, p5, p6, p7, eh0, eh1);
                    mma16816(y1, p4, p5, p6, p7, eh2, eh3);
                }
            }
            __syncthreads();     // B: EW(kt) + P(kt) readers done

            // prefetch EW(kt+1)
            if (kt < qt) {
                const unsigned short* vh = ewh + (size_t)(k0 + BK + ldr) * DIM;
                const unsigned short* vl = ewl + (size_t)(k0 + BK + ldr) * DIM;
#pragma unroll
                for (int j = 0; j < 4; j++) {
                    const int seg = lds0 + j * 8;
                    const uint32_t off = (uint32_t)ldr * 512u + SWZ(ldr, seg * 16);
                    cp16(sb + OFF_EH + off, vh + seg * 8);
                    cp16(sb + OFF_EL + off, vl + seg * 8);
                }
            }
            CP_COMMIT();
            CP_WAIT1();          // K(kt+1) done; EW(kt+1) pending
            __syncthreads();     // C: K(kt+1) visible
        }

        // ---- rowsum reduce ----
        rs0 += __shfl_xor_sync(0xffffffffu, rs0, 1);
        rs0 += __shfl_xor_sync(0xffffffffu, rs0, 2);
        rs1 += __shfl_xor_sync(0xffffffffu, rs1, 1);
        rs1 += __shfl_xor_sync(0xffffffffu, rs1, 2);
        if ((lane & 3) == 0) {
            atomicAdd(&rowsum[row0], rs0);
            atomicAdd(&rowsum[row0 + 8], rs1);
        }
        __syncthreads();

        // ---- scale + write output directly (projection pre-folded) ----
        {
            const float sc0 = 1.f / (rowsum[row0] * (float)(qg0 + 1));
            const float sc1 = 1.f / (rowsum[row0 + 8] * (float)(qg1 + 1));
            float* ob = out + (size_t)b * SEQ * DIM;
#pragma unroll
            for (int nt = 0; nt < 8; nt++) {
                const int col = nw * 64 + nt * 8 + (lane & 3) * 2;
                *(float2*)(ob + (size_t)qg0 * DIM + col) =
                    make_float2(yacc[nt][0] * sc0, yacc[nt][1] * sc0);
                *(float2*)(ob + (size_t)qg1 * DIM + col) =
                    make_float2(yacc[nt][2] * sc1, yacc[nt][3] * sc1);
            }
        }
        __syncthreads();   // pass isolation (smem + rowsum reuse)
    }
}

// ---------------------------------------------------------------------------
extern "C" void kernel_launch(void* const* d_in, const int* in_sizes, int n_in,
                              void* d_out, int out_size) {
    const float *e = nullptr, *p = nullptr, *wo = nullptr;
    for (int i = 0; i < n_in; i++) {
        if      (in_sizes[i] == NE)                e  = (const float*)d_in[i];
        else if (in_sizes[i] == NP)                p  = (const float*)d_in[i];
        else if (in_sizes[i] == DIM * DIM * HEADS) wo = (const float*)d_in[i];
    }

    cudaFuncSetAttribute(attn_kernel, cudaFuncAttributeMaxDynamicSharedMemorySize, SMEM_TOTAL);
    cudaFuncSetAttribute(ew_kernel, cudaFuncAttributeMaxDynamicSharedMemorySize, EW_SMEM);

    split_p_kernel<<<(NP / 4 + 255) / 256, 256>>>((const float4*)p);
    weff_kernel<<<DIM * DIM / 256, 256>>>(wo);
    ew_kernel<<<BATCH * SEQ / 64, 256, EW_SMEM>>>(e);
    attn_kernel<<<dim3(16, BATCH), NTHR, SMEM_TOTAL>>>((float*)d_out);
}

// round 14
// speedup vs baseline: 1.0564x; 1.0564x over previous
#include <cuda_runtime.h>
#include <cuda_bf16.h>
#include <cstdint>

#define BATCH 8
#define SEQ   2048
#define DIM   256
#define HEADS 8
#define BQ 64
#define BK 64
#define NTHR 512
#define NP (BATCH * (SEQ + 1) * DIM)
#define NE (BATCH * SEQ * DIM)

// ---- attn smem byte offsets ----
#define OFF_QH 0
#define OFF_QL 32768
#define OFF_KH 65536
#define OFF_KL 98304
#define OFF_EH 131072          // EW hi tile
#define OFF_EL 163840          // EW lo tile
#define OFF_PH 196608
#define OFF_PL 204800
#define OFF_RS 212992
#define SMEM_TOTAL (OFF_RS + 256)

// ---- ew kernel smem: 128 E rows (hi/lo) + double-buffered W chunks ----
#define EW_EH 0
#define EW_EL 65536
#define EW_W0 131072
#define EW_WSTRIDE 20480       // 256 rows x 80B
#define EW_W1 (EW_W0 + EW_WSTRIDE)
#define EW_SMEM (EW_W1 + EW_WSTRIDE)   // 172032 bytes, 1 CTA/SM, single wave

// pre-split operands (bf16 bits as ushort)
__device__ __align__(16) unsigned short g_ph[NP];
__device__ __align__(16) unsigned short g_pl[NP];
__device__ __align__(16) unsigned short g_Wh[DIM * DIM];
__device__ __align__(16) unsigned short g_Wl[DIM * DIM];
__device__ __align__(16) unsigned short g_ewh[NE];
__device__ __align__(16) unsigned short g_ewl[NE];

// ---- helpers ----
__device__ __forceinline__ uint32_t smem_u32(const void* p) {
    uint32_t a;
    asm("{ .reg .u64 t; cvta.to.shared.u64 t, %1; cvt.u32.u64 %0, t; }" : "=r"(a) : "l"(p));
    return a;
}
__device__ __forceinline__ void cp16(uint32_t dst, const void* src) {
    asm volatile("cp.async.cg.shared.global [%0], [%1], 16;" :: "r"(dst), "l"(src));
}
#define CP_COMMIT() asm volatile("cp.async.commit_group;" ::: "memory")
#define CP_WAIT0()  asm volatile("cp.async.wait_group 0;" ::: "memory")
#define CP_WAIT1()  asm volatile("cp.async.wait_group 1;" ::: "memory")

__device__ __forceinline__ void ldsm4(uint32_t addr, uint32_t& r0, uint32_t& r1, uint32_t& r2, uint32_t& r3) {
    asm volatile("ldmatrix.sync.aligned.m8n8.x4.shared.b16 {%0,%1,%2,%3}, [%4];"
                 : "=r"(r0), "=r"(r1), "=r"(r2), "=r"(r3) : "r"(addr));
}
__device__ __forceinline__ void ldsm4t(uint32_t addr, uint32_t& r0, uint32_t& r1, uint32_t& r2, uint32_t& r3) {
    asm volatile("ldmatrix.sync.aligned.m8n8.x4.trans.shared.b16 {%0,%1,%2,%3}, [%4];"
                 : "=r"(r0), "=r"(r1), "=r"(r2), "=r"(r3) : "r"(addr));
}
__device__ __forceinline__ void mma16816(float* c, uint32_t a0, uint32_t a1, uint32_t a2, uint32_t a3,
                                         uint32_t b0, uint32_t b1) {
    asm volatile("mma.sync.aligned.m16n8k16.row.col.f32.bf16.bf16.f32 "
                 "{%0,%1,%2,%3}, {%4,%5,%6,%7}, {%8,%9}, {%0,%1,%2,%3};"
                 : "+f"(c[0]), "+f"(c[1]), "+f"(c[2]), "+f"(c[3])
                 : "r"(a0), "r"(a1), "r"(a2), "r"(a3), "r"(b0), "r"(b1));
}
__device__ __forceinline__ void split2(float x0, float x1, unsigned& hp, unsigned& lp) {
    __nv_bfloat16 h0 = __float2bfloat16_rn(x0);
    __nv_bfloat16 h1 = __float2bfloat16_rn(x1);
    __nv_bfloat16 l0 = __float2bfloat16_rn(x0 - __bfloat162float(h0));
    __nv_bfloat16 l1 = __float2bfloat16_rn(x1 - __bfloat162float(h1));
    hp = (unsigned)__bfloat16_as_ushort(h0) | ((unsigned)__bfloat16_as_ushort(h1) << 16);
    lp = (unsigned)__bfloat16_as_ushort(l0) | ((unsigned)__bfloat16_as_ushort(l1) << 16);
}
#define SWZ(row, colb) ((uint32_t)(colb) ^ (((uint32_t)(row) & 7u) << 4))

// 512B-row tile: split + store 4 consecutive cols (hi/lo)
__device__ __forceinline__ void store_split4_512(char* bh, char* bl, int row, int col, float4 v) {
    unsigned h0, l0, h1, l1;
    split2(v.x, v.y, h0, l0);
    split2(v.z, v.w, h1, l1);
    uint32_t off = (uint32_t)row * 512u + SWZ(row, col * 2);
    *(uint32_t*)(bh + off) = h0; *(uint32_t*)(bh + off + 4) = h1;
    *(uint32_t*)(bl + off) = l0; *(uint32_t*)(bl + off + 4) = l1;
}

// ---------------------------------------------------------------------------
// split p into hi/lo bf16 (4 x float4 per thread for MLP)
// ---------------------------------------------------------------------------
__global__ void split_p_kernel(const float4* __restrict__ p4) {
    int base = (blockIdx.x * blockDim.x + threadIdx.x) * 4;
    if (base + 3 < NP / 4) {
        float4 v0 = p4[base];
        float4 v1 = p4[base + 1];
        float4 v2 = p4[base + 2];
        float4 v3 = p4[base + 3];
        float4 vv[4] = {v0, v1, v2, v3};
#pragma unroll
        for (int j = 0; j < 4; j++) {
            unsigned h01, l01, h23, l23;
            split2(vv[j].x, vv[j].y, h01, l01);
            split2(vv[j].z, vv[j].w, h23, l23);
            *(uint2*)(g_ph + 4 * (size_t)(base + j)) = make_uint2(h01, h23);
            *(uint2*)(g_pl + 4 * (size_t)(base + j)) = make_uint2(l01, l23);
        }
    } else {
        for (int j = 0; j < 4 && base + j < NP / 4; j++) {
            float4 v = p4[base + j];
            unsigned h01, l01, h23, l23;
            split2(v.x, v.y, h01, l01);
            split2(v.z, v.w, h23, l23);
            *(uint2*)(g_ph + 4 * (size_t)(base + j)) = make_uint2(h01, h23);
            *(uint2*)(g_pl + 4 * (size_t)(base + j)) = make_uint2(l01, l23);
        }
    }
}

// W_eff[n][k] = sum_h W_o[n, h*DIM + k], split
__global__ void weff_kernel(const float* __restrict__ Wo) {
    int t = blockIdx.x * blockDim.x + threadIdx.x;
    int dout = t >> 8, din = t & 255;
    float s = 0.f;
#pragma unroll
    for (int h = 0; h < HEADS; h++)
        s += Wo[(size_t)dout * (DIM * HEADS) + h * DIM + din];
    __nv_bfloat16 hh = __float2bfloat16_rn(s);
    g_Wh[t] = __bfloat16_as_ushort(hh);
    g_Wl[t] = __bfloat16_as_ushort(__float2bfloat16_rn(s - __bfloat162float(hh)));
}

// ---------------------------------------------------------------------------
// EW = E @ Weff^T (16384 x 256), bf16x3, single wave: 128 CTAs x 128 rows,
// 512 threads = 8 m-warps x 2 n-warps, double-buffered W-chunk pipeline.
// W chunk c = k-cols [c*16, c*16+16), 80B/row: [0:32) hi, [32:64) lo.
// ---------------------------------------------------------------------------
__global__ __launch_bounds__(512, 1)
void ew_kernel(const float* __restrict__ e) {
    extern __shared__ char smem[];
    const uint32_t sb = smem_u32(smem);
    const int tid  = threadIdx.x;
    const int lane = tid & 31;
    const int wid  = tid >> 5;
    const int mw   = wid & 7;    // 8 m-warps x 16 rows
    const int nw   = wid >> 3;   // 2 n-warps x 128 dims
    const int rbase = (int)blockIdx.x * 128;

    // load + split E rows (128 x 256 fp32)
    {
        const int r  = tid >> 2;
        const int cb = (tid & 3) * 64;
        const float* er = e + (size_t)(rbase + r) * DIM + cb;
#pragma unroll
        for (int i = 0; i < 16; i++) {
            float4 v = *(const float4*)(er + i * 4);
            store_split4_512(smem + EW_EH, smem + EW_EL, r, cb + i * 4, v);
        }
    }

    // prefetch W chunk 0 into buffer 0 (thread t: row t>>1, half t&1)
    {
        const int wr = tid >> 1, half = tid & 1;
        const uint32_t ro = sb + EW_W0 + (uint32_t)wr * 80u + (uint32_t)half * 32u;
        const unsigned short* ws = (half ? g_Wl : g_Wh) + (size_t)wr * 256;
        cp16(ro, ws); cp16(ro + 16, ws + 8);
        CP_COMMIT();
    }

    float pacc[16][4];
#pragma unroll
    for (int i = 0; i < 16; i++)
#pragma unroll
        for (int j = 0; j < 4; j++) pacc[i][j] = 0.f;

    const int ar = mw * 16 + (lane & 15);
    const uint32_t kb = (uint32_t)(((lane >> 3) & 1) << 4);

    for (int c = 0; c < 16; c++) {
        __syncthreads();    // readers of chunk c-1 done -> safe to overwrite buffer
        if (c < 15) {       // prefetch chunk c+1
            const int wr = tid >> 1, half = tid & 1;
            const uint32_t ro = sb + (((c + 1) & 1) ? EW_W1 : EW_W0)
                              + (uint32_t)wr * 80u + (uint32_t)half * 32u;
            const unsigned short* ws = (half ? g_Wl : g_Wh) + (size_t)wr * 256 + (c + 1) * 16;
            cp16(ro, ws); cp16(ro + 16, ws + 8);
        }
        CP_COMMIT();
        CP_WAIT1();         // chunk c complete (chunk c+1 pending)
        __syncthreads();    // chunk c visible

        const uint32_t wbuf = sb + ((c & 1) ? EW_W1 : EW_W0);
        const uint32_t acb = (uint32_t)(c * 32 + ((lane >> 4) << 4));
        const uint32_t aoff = (uint32_t)ar * 512u + SWZ(ar, acb);
        uint32_t e0, e1, e2, e3, e4, e5, e6, e7;
        ldsm4(sb + EW_EH + aoff, e0, e1, e2, e3);
        ldsm4(sb + EW_EL + aoff, e4, e5, e6, e7);
#pragma unroll
        for (int pt = 0; pt < 8; pt++) {
            const int dout2 = nw * 128 + pt * 16 + (lane & 7) + ((lane >> 4) << 3);
            const uint32_t wrow = wbuf + (uint32_t)dout2 * 80u;
            uint32_t wh0, wh1, wh2, wh3, wl0, wl1, wl2, wl3;
            ldsm4(wrow + kb, wh0, wh1, wh2, wh3);
            ldsm4(wrow + 32 + kb, wl0, wl1, wl2, wl3);
            float* c0 = pacc[2 * pt];
            float* c1 = pacc[2 * pt + 1];
            mma16816(c0, e0, e1, e2, e3, wh0, wh1);
            mma16816(c1, e0, e1, e2, e3, wh2, wh3);
            mma16816(c0, e0, e1, e2, e3, wl0, wl1);
            mma16816(c1, e0, e1, e2, e3, wl2, wl3);
            mma16816(c0, e4, e5, e6, e7, wh0, wh1);
            mma16816(c1, e4, e5, e6, e7, wh2, wh3);
        }
    }

    // write EW split hi/lo
    const int r0 = rbase + mw * 16 + (lane >> 2);
    const int r1 = r0 + 8;
#pragma unroll
    for (int nt = 0; nt < 16; nt++) {
        const int col = nw * 128 + nt * 8 + (lane & 3) * 2;
        unsigned h, l;
        split2(pacc[nt][0], pacc[nt][1], h, l);
        *(uint32_t*)(g_ewh + (size_t)r0 * DIM + col) = h;
        *(uint32_t*)(g_ewl + (size_t)r0 * DIM + col) = l;
        split2(pacc[nt][2], pacc[nt][3], h, l);
        *(uint32_t*)(g_ewh + (size_t)r1 * DIM + col) = h;
        *(uint32_t*)(g_ewl + (size_t)r1 * DIM + col) = l;
    }
}

// ---------------------------------------------------------------------------
// Fused attention (projection pre-folded into EW), mma.sync bf16x3, paired
// q-tiles. 512 threads = 16 warps: 4 mw x 4 nw.  (Proven 183us structure.)
// ---------------------------------------------------------------------------
__global__ __launch_bounds__(NTHR, 1)
void attn_kernel(float* __restrict__ out) {
    extern __shared__ char smem[];
    const uint32_t sb = smem_u32(smem);
    const int tid  = threadIdx.x;
    const int lane = tid & 31;
    const int wid  = tid >> 5;
    const int mw   = wid & 3;
    const int nw   = wid >> 2;
    const int b    = blockIdx.y;
    const unsigned short* ph  = g_ph  + (size_t)b * (SEQ + 1) * DIM;
    const unsigned short* pl  = g_pl  + (size_t)b * (SEQ + 1) * DIM;
    const unsigned short* ewh = g_ewh + (size_t)b * SEQ * DIM;
    const unsigned short* ewl = g_ewl + (size_t)b * SEQ * DIM;
    float* rowsum = (float*)(smem + OFF_RS);

    const int row0 = mw * 16 + (lane >> 2);
    const int ar   = mw * 16 + (lane & 15);
    const int key  = nw * 16 + (lane & 7) + ((lane >> 4) << 3);
    const int ldr  = tid >> 3;
    const int lds0 = tid & 7;

    for (int pass = 0; pass < 2; pass++) {
        const int qt = pass ? (int)blockIdx.x : 31 - (int)blockIdx.x;
        const int q0 = qt * BQ;
        const int qg0 = q0 + row0, qg1 = qg0 + 8;
        const int qgmax = q0 + mw * 16 + 15;
        if (tid < BQ) rowsum[tid] = 0.f;

        // ---- prologue: Q + K(0) (group 1), EW(0) (group 2) ----
        {
            const unsigned short* qh = ph + (size_t)(q0 + ldr + 1) * DIM;
            const unsigned short* ql = pl + (size_t)(q0 + ldr + 1) * DIM;
            const unsigned short* kh = ph + (size_t)ldr * DIM;
            const unsigned short* kl = pl + (size_t)ldr * DIM;
#pragma unroll
            for (int j = 0; j < 4; j++) {
                const int seg = lds0 + j * 8;
                const uint32_t off = (uint32_t)ldr * 512u + SWZ(ldr, seg * 16);
                cp16(sb + OFF_QH + off, qh + seg * 8);
                cp16(sb + OFF_QL + off, ql + seg * 8);
                cp16(sb + OFF_KH + off, kh + seg * 8);
                cp16(sb + OFF_KL + off, kl + seg * 8);
            }
            CP_COMMIT();
            const unsigned short* vh = ewh + (size_t)ldr * DIM;
            const unsigned short* vl = ewl + (size_t)ldr * DIM;
#pragma unroll
            for (int j = 0; j < 4; j++) {
                const int seg = lds0 + j * 8;
                const uint32_t off = (uint32_t)ldr * 512u + SWZ(ldr, seg * 16);
                cp16(sb + OFF_EH + off, vh + seg * 8);
                cp16(sb + OFF_EL + off, vl + seg * 8);
            }
            CP_COMMIT();
        }
        CP_WAIT1();
        __syncthreads();

        float yacc[8][4];
#pragma unroll
        for (int i = 0; i < 8; i++)
#pragma unroll
            for (int j = 0; j < 4; j++) yacc[i][j] = 0.f;
        float rs0 = 0.f, rs1 = 0.f;

        // ---- key-tile loop: entry invariant: K(kt) visible, EW(kt) pending ----
        for (int kt = 0; kt <= qt; kt++) {
            const int k0 = kt * BK;
            const bool sActive = (k0 + nw * 16) <= qgmax;

            float sacc[2][4];
#pragma unroll
            for (int i = 0; i < 2; i++)
#pragma unroll
                for (int j = 0; j < 4; j++) sacc[i][j] = 0.f;
            if (sActive) {
#pragma unroll
                for (int ks = 0; ks < 16; ks++) {
                    const uint32_t acb = (uint32_t)(ks * 32 + ((lane >> 4) << 4));
                    const uint32_t aoff = (uint32_t)ar * 512u + SWZ(ar, acb);
                    uint32_t qh0, qh1, qh2, qh3, ql0, ql1, ql2, ql3;
                    ldsm4(sb + OFF_QH + aoff, qh0, qh1, qh2, qh3);
                    ldsm4(sb + OFF_QL + aoff, ql0, ql1, ql2, ql3);
                    const uint32_t kb = (uint32_t)(ks * 32 + (((lane >> 3) & 1) << 4));
                    const uint32_t koff = (uint32_t)key * 512u + SWZ(key, kb);
                    uint32_t kh0, kh1, kh2, kh3, kl0, kl1, kl2, kl3;
                    ldsm4(sb + OFF_KH + koff, kh0, kh1, kh2, kh3);
                    ldsm4(sb + OFF_KL + koff, kl0, kl1, kl2, kl3);
                    mma16816(sacc[0], qh0, qh1, qh2, qh3, kh0, kh1);
                    mma16816(sacc[1], qh0, qh1, qh2, qh3, kh2, kh3);
                    mma16816(sacc[0], qh0, qh1, qh2, qh3, kl0, kl1);
                    mma16816(sacc[1], qh0, qh1, qh2, qh3, kl2, kl3);
                    mma16816(sacc[0], ql0, ql1, ql2, ql3, kh0, kh1);
                    mma16816(sacc[1], ql0, ql1, ql2, ql3, kh2, kh3);
                }
            }

            // epilogue (register-only): scale/clip/mask/exp; P -> smem
            if (sActive) {
#pragma unroll
                for (int nt = 0; nt < 2; nt++) {
                    const int colL = nw * 16 + nt * 8 + (lane & 3) * 2;
                    const int kgl = k0 + colL;
                    float s00 = fminf(10.f, fmaxf(-10.f, sacc[nt][0] * 0.0625f));
                    float s01 = fminf(10.f, fmaxf(-10.f, sacc[nt][1] * 0.0625f));
                    float s10 = fminf(10.f, fmaxf(-10.f, sacc[nt][2] * 0.0625f));
                    float s11 = fminf(10.f, fmaxf(-10.f, sacc[nt][3] * 0.0625f));
                    float w00 = (kgl     <= qg0) ? __expf(s00) : 0.f;
                    float w01 = (kgl + 1 <= qg0) ? __expf(s01) : 0.f;
                    float w10 = (kgl     <= qg1) ? __expf(s10) : 0.f;
                    float w11 = (kgl + 1 <= qg1) ? __expf(s11) : 0.f;
                    rs0 += w00 + w01;
                    rs1 += w10 + w11;
                    unsigned h, l;
                    uint32_t o0 = (uint32_t)row0 * 128u + SWZ(row0, colL * 2);
                    split2(w00, w01, h, l);
                    *(uint32_t*)(smem + OFF_PH + o0) = h;
                    *(uint32_t*)(smem + OFF_PL + o0) = l;
                    uint32_t o1 = (uint32_t)(row0 + 8) * 128u + SWZ(row0 + 8, colL * 2);
                    split2(w10, w11, h, l);
                    *(uint32_t*)(smem + OFF_PH + o1) = h;
                    *(uint32_t*)(smem + OFF_PL + o1) = l;
                }
            } else {
#pragma unroll
                for (int nt = 0; nt < 2; nt++) {
                    const int colL = nw * 16 + nt * 8 + (lane & 3) * 2;
                    uint32_t o0 = (uint32_t)row0 * 128u + SWZ(row0, colL * 2);
                    *(uint32_t*)(smem + OFF_PH + o0) = 0u;
                    *(uint32_t*)(smem + OFF_PL + o0) = 0u;
                    uint32_t o1 = (uint32_t)(row0 + 8) * 128u + SWZ(row0 + 8, colL * 2);
                    *(uint32_t*)(smem + OFF_PH + o1) = 0u;
                    *(uint32_t*)(smem + OFF_PL + o1) = 0u;
                }
            }

            CP_WAIT0();          // EW(kt) complete
            __syncthreads();     // A: K readers done; P + EW visible

            // prefetch K(kt+1)
            if (kt < qt) {
                const unsigned short* kh = ph + (size_t)(k0 + BK + ldr) * DIM;
                const unsigned short* kl = pl + (size_t)(k0 + BK + ldr) * DIM;
#pragma unroll
                for (int j = 0; j < 4; j++) {
                    const int seg = lds0 + j * 8;
                    const uint32_t off = (uint32_t)ldr * 512u + SWZ(ldr, seg * 16);
                    cp16(sb + OFF_KH + off, kh + seg * 8);
                    cp16(sb + OFF_KL + off, kl + seg * 8);
                }
            }
            CP_COMMIT();

            // AV GEMM (vs EW): warp tile 16 rows x 64 out-dims
#pragma unroll
            for (int ks = 0; ks < 4; ks++) {
                if (k0 + ks * 16 > qgmax) continue;
                const uint32_t acb = (uint32_t)(ks * 32 + ((lane >> 4) << 4));
                const uint32_t aoff = (uint32_t)ar * 128u + SWZ(ar, acb);
                uint32_t p0, p1, p2, p3, p4, p5, p6, p7;
                ldsm4(sb + OFF_PH + aoff, p0, p1, p2, p3);
                ldsm4(sb + OFF_PL + aoff, p4, p5, p6, p7);
                const int key2 = ks * 16 + (lane & 15);
#pragma unroll
                for (int grp = 0; grp < 4; grp++) {
                    const uint32_t dcb = (uint32_t)((nw * 64 + grp * 16 + ((lane >> 4) << 3)) * 2);
                    const uint32_t eoff = (uint32_t)key2 * 512u + SWZ(key2, dcb);
                    uint32_t eh0, eh1, eh2, eh3, el0, el1, el2, el3;
                    ldsm4t(sb + OFF_EH + eoff, eh0, eh1, eh2, eh3);
                    ldsm4t(sb + OFF_EL + eoff, el0, el1, el2, el3);
                    float* y0 = yacc[2 * grp];
                    float* y1 = yacc[2 * grp + 1];
                    mma16816(y0, p0, p1, p2, p3, eh0, eh1);
                    mma16816(y1, p0, p1, p2, p3, eh2, eh3);
                    mma16816(y0, p0, p1, p2, p3, el0, el1);
                    mma16816(y1, p0, p1, p2, p3, el2, el3);
                    mma16816(y0, p4, p5, p6, p7, eh0, eh1);
                    mma16816(y1, p4, p5, p6, p7, eh2, eh3);
                }
            }
            __syncthreads();     // B: EW + P readers done

            // prefetch EW(kt+1)
            if (kt < qt) {
                const unsigned short* vh = ewh + (size_t)(k0 + BK + ldr) * DIM;
                const unsigned short* vl = ewl + (size_t)(k0 + BK + ldr) * DIM;
#pragma unroll
                for (int j = 0; j < 4; j++) {
                    const int seg = lds0 + j * 8;
                    const uint32_t off = (uint32_t)ldr * 512u + SWZ(ldr, seg * 16);
                    cp16(sb + OFF_EH + off, vh + seg * 8);
                    cp16(sb + OFF_EL + off, vl + seg * 8);
                }
            }
            CP_COMMIT();
            CP_WAIT1();          // K(kt+1) done; EW(kt+1) pending
            __syncthreads();     // C: K(kt+1) visible
        }

        // ---- rowsum reduce ----
        rs0 += __shfl_xor_sync(0xffffffffu, rs0, 1);
        rs0 += __shfl_xor_sync(0xffffffffu, rs0, 2);
        rs1 += __shfl_xor_sync(0xffffffffu, rs1, 1);
        rs1 += __shfl_xor_sync(0xffffffffu, rs1, 2);
        if ((lane & 3) == 0) {
            atomicAdd(&rowsum[row0], rs0);
            atomicAdd(&rowsum[row0 + 8], rs1);
        }
        __syncthreads();

        // ---- scale + write output directly ----
        {
            const float sc0 = 1.f / (rowsum[row0] * (float)(qg0 + 1));
            const float sc1 = 1.f / (rowsum[row0 + 8] * (float)(qg1 + 1));
            float* ob = out + (size_t)b * SEQ * DIM;
#pragma unroll
            for (int nt = 0; nt < 8; nt++) {
                const int col = nw * 64 + nt * 8 + (lane & 3) * 2;
                *(float2*)(ob + (size_t)qg0 * DIM + col) =
                    make_float2(yacc[nt][0] * sc0, yacc[nt][1] * sc0);
                *(float2*)(ob + (size_t)qg1 * DIM + col) =
                    make_float2(yacc[nt][2] * sc1, yacc[nt][3] * sc1);
            }
        }
        __syncthreads();   // pass isolation
    }
}

// ---------------------------------------------------------------------------
extern "C" void kernel_launch(void* const* d_in, const int* in_sizes, int n_in,
                              void* d_out, int out_size) {
    const float *e = nullptr, *p = nullptr, *wo = nullptr;
    for (int i = 0; i < n_in; i++) {
        if      (in_sizes[i] == NE)                e  = (const float*)d_in[i];
        else if (in_sizes[i] == NP)                p  = (const float*)d_in[i];
        else if (in_sizes[i] == DIM * DIM * HEADS) wo = (const float*)d_in[i];
    }

    cudaFuncSetAttribute(attn_kernel, cudaFuncAttributeMaxDynamicSharedMemorySize, SMEM_TOTAL);
    cudaFuncSetAttribute(ew_kernel, cudaFuncAttributeMaxDynamicSharedMemorySize, EW_SMEM);

    split_p_kernel<<<(NP / 16 + 255) / 256, 256>>>((const float4*)p);
    weff_kernel<<<DIM * DIM / 256, 256>>>(wo);
    ew_kernel<<<BATCH * SEQ / 128, 512, EW_SMEM>>>(e);
    attn_kernel<<<dim3(16, BATCH), NTHR, SMEM_TOTAL>>>((float*)d_out);
}